// round 14
// baseline (speedup 1.0000x reference)
#include <cuda_runtime.h>
#include <math.h>
#include <stdint.h>

#define NN 4096
#define PP 128
#define LL 32
#define ASPLIT 8
#define BSPLIT 6
#define CHA (NN / ASPLIT)   // 512
#define BCH 704             // beta split size (5*704 + 576 = 4096)

// ---------------- scratch (device globals; no allocation) ----------------
__device__ float g_x2[NN];
__device__ float g_d2[(size_t)NN * NN];    // clamped squared distances (64 MB)
__device__ int   g_mdbits;                 // atomicMax of d2c as ordered int
__device__ float g_muP[ASPLIT * NN * PP];  // unnormalized mu partials
__device__ float g_saP[ASPLIT * NN];       // alpha weight-sum partials
__device__ float g_eZP[BSPLIT * NN * PP];  // unnormalized eZ partials
__device__ float g_sbP[BSPLIT * NN];       // beta weight-sum partials
__device__ float g_U[NN * PP];
__device__ float g_un2[NN];
__device__ float g_yU[NN];

// ---------------- f32x2 packed helpers ----------------
typedef unsigned long long ull;

__device__ __forceinline__ void fma2(ull& d, ull a, ull b) {
    asm("fma.rn.f32x2 %0, %1, %2, %0;" : "+l"(d) : "l"(a), "l"(b));
}
__device__ __forceinline__ ull pack2(float lo, float hi) {
    ull r;
    asm("mov.b64 %0, {%1, %2};" : "=l"(r) : "f"(lo), "f"(hi));
    return r;
}
__device__ __forceinline__ float2 unpack2(ull v) {
    float2 r;
    asm("mov.b64 {%0, %1}, %2;" : "=f"(r.x), "=f"(r.y) : "l"(v));
    return r;
}

// ---------------- tf32 helpers ----------------
__device__ __forceinline__ void mma_tf32(float& c0, float& c1, float& c2, float& c3,
                                         uint32_t a0, uint32_t a1, uint32_t a2, uint32_t a3,
                                         uint32_t b0, uint32_t b1) {
    asm("mma.sync.aligned.m16n8k8.row.col.f32.tf32.tf32.f32 "
        "{%0,%1,%2,%3}, {%4,%5,%6,%7}, {%8,%9}, {%0,%1,%2,%3};"
        : "+f"(c0), "+f"(c1), "+f"(c2), "+f"(c3)
        : "r"(a0), "r"(a1), "r"(a2), "r"(a3), "r"(b0), "r"(b1));
}
__device__ __forceinline__ float tf32_round(float v) {
    uint32_t u;
    asm("cvt.rna.tf32.f32 %0, %1;" : "=r"(u) : "f"(v));
    return __uint_as_float(u);
}

// ---------------- tiny init ----------------
__global__ void k_zero(float* out) {
    g_mdbits = 0;
    out[0] = 0.0f;
}

// ---------------- x2[i] = ||x_i||^2 ----------------
__global__ void k_x2(const float* __restrict__ x) {
    int row  = blockIdx.x;
    int lane = threadIdx.x;              // 32 threads
    const float4* x4 = (const float4*)x;
    float4 v = x4[row * 32 + lane];
    float s = v.x * v.x + v.y * v.y + v.z * v.z + v.w * v.w;
    #pragma unroll
    for (int o = 16; o; o >>= 1) s += __shfl_xor_sync(0xffffffffu, s, o);
    if (lane == 0) g_x2[row] = s;
}

// ---------------- Gram / dist^2 via tf32 mma (128x128 tile, full grid) ----------------
__global__ __launch_bounds__(256, 2) void k_gram(const float* __restrict__ x) {
    __shared__ float As[8][140];   // As[kk][i]  (k-major)
    __shared__ float Bs[8][140];   // Bs[kk][j]
    __shared__ float redmax[8];
    int jb = blockIdx.x * 128, ib = blockIdx.y * 128;
    int t    = threadIdx.x;
    int w    = t >> 5;
    int lane = t & 31;
    int g    = lane >> 2;           // 0..7
    int t4   = lane & 3;            // 0..3
    int mwarp = (w & 1) * 64;       // warp covers m 64, n 32
    int nwarp = (w >> 1) * 32;

    float c[4][4][4];               // [mt][nt][{c0..c3}]
    #pragma unroll
    for (int mt = 0; mt < 4; mt++)
        #pragma unroll
        for (int nt = 0; nt < 4; nt++)
            #pragma unroll
            for (int q = 0; q < 4; q++) c[mt][nt][q] = 0.0f;

    int lr = t >> 1, lc = (t & 1) * 4;
    for (int k0 = 0; k0 < PP; k0 += 8) {
        float4 av = *(const float4*)(x + (size_t)(ib + lr) * PP + k0 + lc);
        float4 bv = *(const float4*)(x + (size_t)(jb + lr) * PP + k0 + lc);
        __syncthreads();
        As[lc + 0][lr] = av.x; As[lc + 1][lr] = av.y;
        As[lc + 2][lr] = av.z; As[lc + 3][lr] = av.w;
        Bs[lc + 0][lr] = bv.x; Bs[lc + 1][lr] = bv.y;
        Bs[lc + 2][lr] = bv.z; Bs[lc + 3][lr] = bv.w;
        __syncthreads();

        uint32_t a[4][4], b[4][2];
        #pragma unroll
        for (int mt = 0; mt < 4; mt++) {
            int m0 = mwarp + mt * 16;
            a[mt][0] = __float_as_uint(As[t4][m0 + g]);
            a[mt][1] = __float_as_uint(As[t4][m0 + g + 8]);
            a[mt][2] = __float_as_uint(As[t4 + 4][m0 + g]);
            a[mt][3] = __float_as_uint(As[t4 + 4][m0 + g + 8]);
        }
        #pragma unroll
        for (int nt = 0; nt < 4; nt++) {
            int n0 = nwarp + nt * 8;
            b[nt][0] = __float_as_uint(Bs[t4][n0 + g]);
            b[nt][1] = __float_as_uint(Bs[t4 + 4][n0 + g]);
        }
        #pragma unroll
        for (int mt = 0; mt < 4; mt++)
            #pragma unroll
            for (int nt = 0; nt < 4; nt++)
                mma_tf32(c[mt][nt][0], c[mt][nt][1], c[mt][nt][2], c[mt][nt][3],
                         a[mt][0], a[mt][1], a[mt][2], a[mt][3],
                         b[nt][0], b[nt][1]);
    }

    // epilogue: d2 = xi2 + xj2 - 2G, clamp, store (row-pair float2), track max
    float xj2A[4], xj2B[4];
    #pragma unroll
    for (int nt = 0; nt < 4; nt++) {
        int cA = jb + nwarp + nt * 8 + 2 * t4;
        xj2A[nt] = __ldg(g_x2 + cA);
        xj2B[nt] = __ldg(g_x2 + cA + 1);
    }
    float lmax = 0.0f;
    #pragma unroll
    for (int mt = 0; mt < 4; mt++) {
        int r0 = ib + mwarp + mt * 16 + g;
        int r1 = r0 + 8;
        float xi2a = __ldg(g_x2 + r0);
        float xi2b = __ldg(g_x2 + r1);
        #pragma unroll
        for (int nt = 0; nt < 4; nt++) {
            int cA = jb + nwarp + nt * 8 + 2 * t4;
            float d00 = fmaxf(xi2a + xj2A[nt] - 2.0f * c[mt][nt][0], 1e-12f);
            float d01 = fmaxf(xi2a + xj2B[nt] - 2.0f * c[mt][nt][1], 1e-12f);
            float d10 = fmaxf(xi2b + xj2A[nt] - 2.0f * c[mt][nt][2], 1e-12f);
            float d11 = fmaxf(xi2b + xj2B[nt] - 2.0f * c[mt][nt][3], 1e-12f);
            lmax = fmaxf(lmax, fmaxf(fmaxf(d00, d01), fmaxf(d10, d11)));
            float2 s0 = { d00, d01 };
            float2 s1 = { d10, d11 };
            *(float2*)(g_d2 + (size_t)r0 * NN + cA) = s0;
            *(float2*)(g_d2 + (size_t)r1 * NN + cA) = s1;
        }
    }
    #pragma unroll
    for (int o = 16; o; o >>= 1)
        lmax = fmaxf(lmax, __shfl_xor_sync(0xffffffffu, lmax, o));
    if (lane == 0) redmax[w] = lmax;
    __syncthreads();
    if (t == 0) {
        float m = redmax[0];
        #pragma unroll
        for (int wgi = 1; wgi < 8; wgi++) m = fmaxf(m, redmax[wgi]);
        atomicMax(&g_mdbits, __float_as_int(m));
    }
}

// ---------------- alpha pass: mu via tf32 mma (64 j per block, i-tile 32) ----------------
__global__ __launch_bounds__(256, 3) void k_alpha(const float* __restrict__ x,
                                                  const float* __restrict__ r0p) {
    extern __shared__ float sm[];
    float* XiT = sm;                  // 128 * 33 (x transposed: XiT[p][i])
    float* ws  = XiT + 128 * 33;      // 64 * 33  (ws[j][i])
    float* red = ws + 64 * 33;        // 8 * 64
    int jb  = blockIdx.x * 64;
    int sid = blockIdx.y;
    int t   = threadIdx.x;
    int jj = t & 31, grp = t >> 5;
    int lane = t & 31, w = t >> 5;
    int g = lane >> 2, t4 = lane & 3;
    int mj = (w >> 1) * 16;           // warp j-tile base (0,16,32,48)
    int nh = (w & 1) * 64;            // warp p-half base (0,64); 8 n-tiles of 8

    float md     = sqrtf(__int_as_float(g_mdbits));
    float r0e    = fminf(__ldg(r0p), md);
    float rr     = r0e * r0e;
    float inv_rr = 1.0f / rr;

    float c[8][4];                    // accumulators: mu fragments, live across i-loop
    #pragma unroll
    for (int nt = 0; nt < 8; nt++)
        #pragma unroll
        for (int q = 0; q < 4; q++) c[nt][q] = 0.0f;
    float sa0 = 0.0f, sa1 = 0.0f;

    int ibeg = sid * CHA, iend = ibeg + CHA;
    for (int ib = ibeg; ib < iend; ib += 32) {
        // XiT fill: coalesced LDG, conflict-free STS (bank = p+i)
        #pragma unroll
        for (int u = 0; u < 16; u++) {
            int idx = t + u * 256;      // 0..4095
            int i = idx >> 7, p = idx & 127;
            XiT[p * 33 + i] = x[(size_t)(ib + i) * PP + p];
        }
        // weight phase: 8 weights/thread, stored [j][i], tf32-rounded for num/den consistency
        #pragma unroll
        for (int s = 0; s < 4; s++) {
            int il = grp * 4 + s;
            size_t base = (size_t)(ib + il) * NN + jb + jj;
            float d0 = g_d2[base];
            float d1 = g_d2[base + 32];
            float w0 = 0.0f, w1 = 0.0f;
            if (d0 < rr) { float b = 1.0f - d0 * inv_rr; w0 = b * b * b; }
            if (d1 < rr) { float b = 1.0f - d1 * inv_rr; w1 = b * b * b; }
            w0 = tf32_round(w0);
            w1 = tf32_round(w1);
            ws[jj * 33 + il]        = w0;
            ws[(jj + 32) * 33 + il] = w1;
            sa0 += w0; sa1 += w1;
        }
        __syncthreads();
        // mma phase: mu[j][p] += ws[j][i] * XiT[p][i]
        #pragma unroll
        for (int k0 = 0; k0 < 32; k0 += 8) {
            uint32_t a0 = __float_as_uint(ws[(mj + g) * 33 + k0 + t4]);
            uint32_t a1 = __float_as_uint(ws[(mj + g + 8) * 33 + k0 + t4]);
            uint32_t a2 = __float_as_uint(ws[(mj + g) * 33 + k0 + t4 + 4]);
            uint32_t a3 = __float_as_uint(ws[(mj + g + 8) * 33 + k0 + t4 + 4]);
            #pragma unroll
            for (int nt = 0; nt < 8; nt++) {
                int n0 = nh + nt * 8;
                uint32_t b0 = __float_as_uint(XiT[(n0 + g) * 33 + k0 + t4]);
                uint32_t b1 = __float_as_uint(XiT[(n0 + g) * 33 + k0 + t4 + 4]);
                mma_tf32(c[nt][0], c[nt][1], c[nt][2], c[nt][3],
                         a0, a1, a2, a3, b0, b1);
            }
        }
        __syncthreads();
    }

    // sa reduce across groups
    red[grp * 64 + jj]      = sa0;
    red[grp * 64 + 32 + jj] = sa1;
    __syncthreads();
    if (t < 64) {
        float s2 = 0.0f;
        #pragma unroll
        for (int gg = 0; gg < 8; gg++) s2 += red[gg * 64 + t];
        g_saP[sid * NN + jb + t] = s2;
    }
    // mu fragment store: rows j = jb+mj+g (+8), cols p = nh + nt*8 + 2*t4
    #pragma unroll
    for (int nt = 0; nt < 8; nt++) {
        int p  = nh + nt * 8 + 2 * t4;
        int j0 = jb + mj + g;
        int j1 = j0 + 8;
        float2 s0 = { c[nt][0], c[nt][1] };
        float2 s1 = { c[nt][2], c[nt][3] };
        *(float2*)(g_muP + ((size_t)sid * NN + j0) * PP + p) = s0;
        *(float2*)(g_muP + ((size_t)sid * NN + j1) * PP + p) = s1;
    }
}

// ---------------- finalize mu; U = x - mu, ||U||^2, <y,U> ----------------
__global__ void k_U(const float* __restrict__ x) {
    int row = blockIdx.x;
    int p   = threadIdx.x;  // 128
    float xv = x[(size_t)row * PP + p];

    float num = 0.0f, den = 0.0f;
    #pragma unroll
    for (int s = 0; s < ASPLIT; s++) {
        num += g_muP[((size_t)s * NN + row) * PP + p];
        den += g_saP[s * NN + row];
    }
    float m = (den > 0.0f) ? num / den : xv;   // NaN-guard fallback to y

    float u = xv - m;
    g_U[(size_t)row * PP + p] = u;
    float a = u * u, b = xv * u;
    #pragma unroll
    for (int o = 16; o; o >>= 1) {
        a += __shfl_xor_sync(0xffffffffu, a, o);
        b += __shfl_xor_sync(0xffffffffu, b, o);
    }
    __shared__ float ra[4], rb[4];
    if ((p & 31) == 0) { ra[p >> 5] = a; rb[p >> 5] = b; }
    __syncthreads();
    if (p == 0) {
        g_un2[row] = ra[0] + ra[1] + ra[2] + ra[3];
        g_yU[row]  = rb[0] + rb[1] + rb[2] + rb[3];
    }
}

// ---------------- weight2 ----------------
__device__ __forceinline__ float wfun2(float d, float r) {
    if (d < 0.5f * r) return 1.0f;
    if (d >= r) return 0.0f;
    float tq = (2.0f * d - r) / r;
    float b  = 1.0f - tq * tq;
    return b * b * b;
}

// ---------------- beta pass: ps via tf32 mma, eZ via f32x2 ----------------
__global__ __launch_bounds__(256, 3) void k_beta(const float* __restrict__ x,
                                                 const float* __restrict__ r1p,
                                                 const float* __restrict__ r2p) {
    extern __shared__ float sm[];
    float* Us  = sm;                   // 64*132
    float* Xi  = Us + 64 * 132;        // 32*132 (pad 132: mma A-frag conflict-free)
    float* ws  = Xi + 32 * 132;        // 32*64
    float* psb = ws + 32 * 64;         // 32*66 (ps tile buffer)
    float* red = psb + 32 * 66;        // 8*64
    int jb  = blockIdx.x * 64;
    int sid = blockIdx.y;
    int t   = threadIdx.x;
    int jj = t & 31, grp = t >> 5;
    int lane = t & 31, w = t >> 5;
    int g = lane >> 2, t4 = lane & 3;
    int mb = (w & 1) * 16;            // warp m-tile base (i rows)
    int nw = (w >> 1) * 16;           // warp n base (j), two n-tiles nw, nw+8

    float md  = sqrtf(__int_as_float(g_mdbits));
    float r1e = fminf(__ldg(r1p), md);
    float r2e = fminf(__ldg(r2p), md);

    #pragma unroll
    for (int u = 0; u < 32; u++) {
        int idx = t + u * 256;                   // 0..8191
        int r = idx >> 7, c = idx & 127;
        Us[r * 132 + c] = g_U[(size_t)(jb + r) * PP + c];
    }
    __syncthreads();

    float un2_0 = g_un2[jb + jj],      yu0 = g_yU[jb + jj];
    float un2_1 = g_un2[jb + 32 + jj], yu1 = g_yU[jb + 32 + jj];

    ull accP[2][8];
    #pragma unroll
    for (int h = 0; h < 2; h++)
        #pragma unroll
        for (int q = 0; q < 8; q++) accP[h][q] = 0ull;
    float sb0 = 0.0f, sb1 = 0.0f;

    const float4* x4g = (const float4*)x;

    int ibeg = sid * BCH;
    int iend = min(NN, ibeg + BCH);
    for (int ib = ibeg; ib < iend; ib += 32) {
        // Xi tile fill (32 rows, padded stride 132)
        #pragma unroll
        for (int u = 0; u < 4; u++) {
            int idx = t + u * 256;         // float4 index 0..1023
            int r = idx >> 5, c4 = idx & 31;
            *(float4*)(Xi + r * 132 + c4 * 4) = x4g[ib * 32 + idx];
        }
        // d2 into registers (independent loads; overlap Xi fill latency)
        float d0r[4], d1r[4];
        #pragma unroll
        for (int s = 0; s < 4; s++) {
            size_t base = (size_t)(ib + grp * 4 + s) * NN + jb + jj;
            d0r[s] = g_d2[base];
            d1r[s] = g_d2[base + 32];
        }
        __syncthreads();

        // ps[i][j] = sum_k Xi[i][k] * U[j][k]  via tf32 mma (warp: m16 x n16, K=128)
        float cc[2][4];
        #pragma unroll
        for (int nt = 0; nt < 2; nt++)
            #pragma unroll
            for (int q = 0; q < 4; q++) cc[nt][q] = 0.0f;
        #pragma unroll
        for (int k0 = 0; k0 < PP; k0 += 8) {
            uint32_t a0 = __float_as_uint(Xi[(mb + g) * 132 + k0 + t4]);
            uint32_t a1 = __float_as_uint(Xi[(mb + g + 8) * 132 + k0 + t4]);
            uint32_t a2 = __float_as_uint(Xi[(mb + g) * 132 + k0 + t4 + 4]);
            uint32_t a3 = __float_as_uint(Xi[(mb + g + 8) * 132 + k0 + t4 + 4]);
            #pragma unroll
            for (int nt = 0; nt < 2; nt++) {
                int n0 = nw + nt * 8;
                uint32_t b0 = __float_as_uint(Us[(n0 + g) * 132 + k0 + t4]);
                uint32_t b1 = __float_as_uint(Us[(n0 + g) * 132 + k0 + t4 + 4]);
                mma_tf32(cc[nt][0], cc[nt][1], cc[nt][2], cc[nt][3],
                         a0, a1, a2, a3, b0, b1);
            }
        }
        // spill ps fragments to smem
        #pragma unroll
        for (int nt = 0; nt < 2; nt++) {
            int n0 = nw + nt * 8;
            float2 p01 = { cc[nt][0], cc[nt][1] };
            float2 p23 = { cc[nt][2], cc[nt][3] };
            *(float2*)(psb + (mb + g) * 66 + n0 + 2 * t4)     = p01;
            *(float2*)(psb + (mb + g + 8) * 66 + n0 + 2 * t4) = p23;
        }
        __syncthreads();

        // weights
        #pragma unroll
        for (int s = 0; s < 4; s++) {
            int il = grp * 4 + s;
            float d0 = d0r[s];
            float d1 = d1r[s];
            float ps0 = psb[il * 66 + jj];
            float ps1 = psb[il * 66 + 32 + jj];
            float psv0 = ps0 - yu0;
            float psv1 = ps1 - yu1;
            float du2_0 = fmaxf(psv0 * psv0 * un2_0, 1e-6f);
            float du2_1 = fmaxf(psv1 * psv1 * un2_1, 1e-6f);
            float dv0 = sqrtf(fmaxf(d0 - du2_0, 1e-6f));
            float dv1 = sqrtf(fmaxf(d1 - du2_1, 1e-6f));
            float du0 = sqrtf(du2_0);
            float du1 = sqrtf(du2_1);
            float w0 = wfun2(dv0, r1e) * wfun2(du0, r2e);
            float w1 = wfun2(dv1, r1e) * wfun2(du1, r2e);
            ws[il * 64 + jj]      = w0;
            ws[il * 64 + 32 + jj] = w1;
            sb0 += w0; sb1 += w1;
        }
        __syncthreads();
        // accumulate eZ (fp32 f32x2; Xi rows are 33 ull2 wide incl. pad)
        const ulonglong2* Xu = (const ulonglong2*)Xi;
        #pragma unroll 2
        for (int i = 0; i < 32; i++) {
            float w0 = ws[i * 64 + jj];
            float w1 = ws[i * 64 + 32 + jj];
            ull w0p = pack2(w0, w0);
            ull w1p = pack2(w1, w1);
            ulonglong2 q0 = Xu[i * 33 + grp * 4 + 0];
            ulonglong2 q1 = Xu[i * 33 + grp * 4 + 1];
            ulonglong2 q2 = Xu[i * 33 + grp * 4 + 2];
            ulonglong2 q3 = Xu[i * 33 + grp * 4 + 3];
            ull xp[8] = { q0.x, q0.y, q1.x, q1.y, q2.x, q2.y, q3.x, q3.y };
            #pragma unroll
            for (int q = 0; q < 8; q++) {
                fma2(accP[0][q], w0p, xp[q]);
                fma2(accP[1][q], w1p, xp[q]);
            }
        }
        __syncthreads();
    }

    red[grp * 64 + jj]      = sb0;
    red[grp * 64 + 32 + jj] = sb1;
    __syncthreads();
    if (t < 64) {
        float s2 = 0.0f;
        #pragma unroll
        for (int gg = 0; gg < 8; gg++) s2 += red[gg * 64 + t];
        g_sbP[sid * NN + jb + t] = s2;
    }
    #pragma unroll
    for (int h = 0; h < 2; h++) {
        int j = jb + h * 32 + jj;
        float* dst = g_eZP + ((size_t)sid * NN + j) * PP + grp * 16;
        #pragma unroll
        for (int q = 0; q < 8; q++)
            *(float2*)(dst + 2 * q) = unpack2(accP[h][q]);
    }
}

// ---------------- fused eZ-finalize + MLP + MSE loss ----------------
__device__ __forceinline__ float gelu_exact(float v) {
    return 0.5f * v * (1.0f + erff(v * 0.70710678118654752f));
}

__global__ void k_mlp(const float* __restrict__ x,
                      const float* __restrict__ We1, const float* __restrict__ be1,
                      const float* __restrict__ We2, const float* __restrict__ be2,
                      const float* __restrict__ Wd1, const float* __restrict__ bd1,
                      const float* __restrict__ Wd2, const float* __restrict__ bd2,
                      float* __restrict__ out) {
    __shared__ float We1s[32 * 129];
    __shared__ float Wd2s[128 * 33];
    __shared__ float We2s[32 * 33];
    __shared__ float Wd1s[32 * 33];
    __shared__ float be1s[32], be2s[32], bd1s[32], bd2s[128];
    int t = threadIdx.x;
    for (int idx = t; idx < 32 * 128; idx += 256)
        We1s[(idx >> 7) * 129 + (idx & 127)] = We1[idx];
    for (int idx = t; idx < 128 * 32; idx += 256)
        Wd2s[(idx >> 5) * 33 + (idx & 31)] = Wd2[idx];
    for (int idx = t; idx < 32 * 32; idx += 256) {
        We2s[(idx >> 5) * 33 + (idx & 31)] = We2[idx];
        Wd1s[(idx >> 5) * 33 + (idx & 31)] = Wd1[idx];
    }
    if (t < 32) { be1s[t] = be1[t]; be2s[t] = be2[t]; bd1s[t] = bd1[t]; }
    if (t < 128) bd2s[t] = bd2[t];
    __syncthreads();

    int lane = t & 31;
    int warp = t >> 5;
    int gw = blockIdx.x * 8 + warp;
    int nw = gridDim.x * 8;
    float part = 0.0f;

    for (int row = gw; row < NN; row += nw) {
        float den = 0.0f;
        #pragma unroll
        for (int s = 0; s < BSPLIT; s++) den += g_sbP[s * NN + row];
        float y0 = 0.0f, y1 = 0.0f, y2 = 0.0f, y3 = 0.0f;
        #pragma unroll
        for (int s = 0; s < BSPLIT; s++) {
            const float* pr = g_eZP + ((size_t)s * NN + row) * PP;
            y0 += pr[lane];       y1 += pr[32 + lane];
            y2 += pr[64 + lane];  y3 += pr[96 + lane];
        }
        if (den > 0.0f) {
            float inv = 1.0f / den;
            y0 *= inv; y1 *= inv; y2 *= inv; y3 *= inv;
        } else {
            const float* xr = x + (size_t)row * PP;
            y0 = xr[lane];      y1 = xr[32 + lane];
            y2 = xr[64 + lane]; y3 = xr[96 + lane];
        }

        float h = be1s[lane];
        const float* wrow = We1s + lane * 129;
        #pragma unroll 8
        for (int k = 0; k < 32; k++) {
            h = fmaf(__shfl_sync(0xffffffffu, y0, k), wrow[k], h);
            h = fmaf(__shfl_sync(0xffffffffu, y1, k), wrow[32 + k], h);
            h = fmaf(__shfl_sync(0xffffffffu, y2, k), wrow[64 + k], h);
            h = fmaf(__shfl_sync(0xffffffffu, y3, k), wrow[96 + k], h);
        }
        h = gelu_exact(h);

        float z = be2s[lane];
        const float* w2row = We2s + lane * 33;
        #pragma unroll
        for (int m = 0; m < 32; m++)
            z = fmaf(__shfl_sync(0xffffffffu, h, m), w2row[m], z);

        float h2 = bd1s[lane];
        const float* w3row = Wd1s + lane * 33;
        #pragma unroll
        for (int m = 0; m < 32; m++)
            h2 = fmaf(__shfl_sync(0xffffffffu, z, m), w3row[m], h2);
        h2 = gelu_exact(h2);

        float xh[4];
        #pragma unroll
        for (int q = 0; q < 4; q++) xh[q] = bd2s[q * 32 + lane];
        #pragma unroll
        for (int m = 0; m < 32; m++) {
            float hm = __shfl_sync(0xffffffffu, h2, m);
            #pragma unroll
            for (int q = 0; q < 4; q++)
                xh[q] = fmaf(hm, Wd2s[(q * 32 + lane) * 33 + m], xh[q]);
        }
        #pragma unroll
        for (int q = 0; q < 4; q++) {
            int p = q * 32 + lane;
            float s   = 1.0f / (1.0f + expf(-xh[q]));
            float dlt = x[(size_t)row * PP + p] - s;
            part = fmaf(dlt, dlt, part);
        }
    }
    #pragma unroll
    for (int o = 16; o; o >>= 1) part += __shfl_xor_sync(0xffffffffu, part, o);
    if (lane == 0) atomicAdd(out, part * (1.0f / ((float)NN * (float)PP)));
}

// ---------------- launch ----------------
extern "C" void kernel_launch(void* const* d_in, const int* in_sizes, int n_in,
                              void* d_out, int out_size) {
    const float* x   = (const float*)d_in[0];
    const float* r0  = (const float*)d_in[1];
    const float* r1  = (const float*)d_in[2];
    const float* r2  = (const float*)d_in[3];
    const float* We1 = (const float*)d_in[4];
    const float* be1 = (const float*)d_in[5];
    const float* We2 = (const float*)d_in[6];
    const float* be2 = (const float*)d_in[7];
    const float* Wd1 = (const float*)d_in[8];
    const float* bd1 = (const float*)d_in[9];
    const float* Wd2 = (const float*)d_in[10];
    const float* bd2 = (const float*)d_in[11];
    float* out = (float*)d_out;

    size_t smA = (size_t)(128 * 33 + 64 * 33 + 8 * 64) * sizeof(float);           // 27392
    size_t smB = (size_t)(64 * 132 + 32 * 132 + 32 * 64 + 32 * 66 + 8 * 64) * sizeof(float); // 69376
    cudaFuncSetAttribute(k_alpha, cudaFuncAttributeMaxDynamicSharedMemorySize, (int)smA);
    cudaFuncSetAttribute(k_beta,  cudaFuncAttributeMaxDynamicSharedMemorySize, (int)smB);

    k_zero<<<1, 1>>>(out);
    k_x2<<<NN, 32>>>(x);
    k_gram<<<dim3(32, 32), 256>>>(x);
    k_alpha<<<dim3(64, ASPLIT), 256, smA>>>(x, r0);
    k_U<<<NN, 128>>>(x);
    k_beta<<<dim3(64, BSPLIT), 256, smB>>>(x, r1, r2);
    k_mlp<<<128, 256>>>(x, We1, be1, We2, be2, Wd1, bd1, Wd2, bd2, out);
}

// round 16
// speedup vs baseline: 1.5567x; 1.5567x over previous
#include <cuda_runtime.h>
#include <math.h>
#include <stdint.h>

#define NN 4096
#define PP 128
#define LL 32
#define ASPLIT 8
#define BSPLIT 6
#define CHA (NN / ASPLIT)   // 512
#define BCH 704             // beta split size (5*704 + 576 = 4096)

// ---------------- scratch (device globals; no allocation) ----------------
__device__ float g_x2[NN];
__device__ float g_d2[(size_t)NN * NN];    // clamped squared distances (64 MB)
__device__ int   g_mdbits;                 // atomicMax of d2c as ordered int
__device__ float g_muP[ASPLIT * NN * PP];  // unnormalized mu partials
__device__ float g_saP[ASPLIT * NN];       // alpha weight-sum partials
__device__ float g_eZP[BSPLIT * NN * PP];  // unnormalized eZ partials
__device__ float g_sbP[BSPLIT * NN];       // beta weight-sum partials
__device__ float g_U[NN * PP];
__device__ float g_un2[NN];
__device__ float g_yU[NN];

// ---------------- f32x2 packed helpers ----------------
typedef unsigned long long ull;

__device__ __forceinline__ void fma2(ull& d, ull a, ull b) {
    asm("fma.rn.f32x2 %0, %1, %2, %0;" : "+l"(d) : "l"(a), "l"(b));
}
__device__ __forceinline__ ull pack2(float lo, float hi) {
    ull r;
    asm("mov.b64 %0, {%1, %2};" : "=l"(r) : "f"(lo), "f"(hi));
    return r;
}
__device__ __forceinline__ float2 unpack2(ull v) {
    float2 r;
    asm("mov.b64 {%0, %1}, %2;" : "=f"(r.x), "=f"(r.y) : "l"(v));
    return r;
}

// ---------------- tf32 helpers ----------------
__device__ __forceinline__ void mma_tf32(float& c0, float& c1, float& c2, float& c3,
                                         uint32_t a0, uint32_t a1, uint32_t a2, uint32_t a3,
                                         uint32_t b0, uint32_t b1) {
    asm("mma.sync.aligned.m16n8k8.row.col.f32.tf32.tf32.f32 "
        "{%0,%1,%2,%3}, {%4,%5,%6,%7}, {%8,%9}, {%0,%1,%2,%3};"
        : "+f"(c0), "+f"(c1), "+f"(c2), "+f"(c3)
        : "r"(a0), "r"(a1), "r"(a2), "r"(a3), "r"(b0), "r"(b1));
}
__device__ __forceinline__ float tf32_round(float v) {
    uint32_t u;
    asm("cvt.rna.tf32.f32 %0, %1;" : "=r"(u) : "f"(v));
    return __uint_as_float(u);
}

// ---------------- tiny init ----------------
__global__ void k_zero(float* out) {
    g_mdbits = 0;
    out[0] = 0.0f;
}

// ---------------- x2[i] = ||x_i||^2 ----------------
__global__ void k_x2(const float* __restrict__ x) {
    int row  = blockIdx.x;
    int lane = threadIdx.x;              // 32 threads
    const float4* x4 = (const float4*)x;
    float4 v = x4[row * 32 + lane];
    float s = v.x * v.x + v.y * v.y + v.z * v.z + v.w * v.w;
    #pragma unroll
    for (int o = 16; o; o >>= 1) s += __shfl_xor_sync(0xffffffffu, s, o);
    if (lane == 0) g_x2[row] = s;
}

// ---------------- Gram / dist^2 via tf32 mma (128x128 tile, full grid) ----------------
__global__ __launch_bounds__(256, 2) void k_gram(const float* __restrict__ x) {
    __shared__ float As[8][140];   // As[kk][i]  (k-major)
    __shared__ float Bs[8][140];   // Bs[kk][j]
    __shared__ float redmax[8];
    int jb = blockIdx.x * 128, ib = blockIdx.y * 128;
    int t    = threadIdx.x;
    int w    = t >> 5;
    int lane = t & 31;
    int g    = lane >> 2;           // 0..7
    int t4   = lane & 3;            // 0..3
    int mwarp = (w & 1) * 64;       // warp covers m 64, n 32
    int nwarp = (w >> 1) * 32;

    float c[4][4][4];               // [mt][nt][{c0..c3}]
    #pragma unroll
    for (int mt = 0; mt < 4; mt++)
        #pragma unroll
        for (int nt = 0; nt < 4; nt++)
            #pragma unroll
            for (int q = 0; q < 4; q++) c[mt][nt][q] = 0.0f;

    int lr = t >> 1, lc = (t & 1) * 4;
    for (int k0 = 0; k0 < PP; k0 += 8) {
        float4 av = *(const float4*)(x + (size_t)(ib + lr) * PP + k0 + lc);
        float4 bv = *(const float4*)(x + (size_t)(jb + lr) * PP + k0 + lc);
        __syncthreads();
        As[lc + 0][lr] = av.x; As[lc + 1][lr] = av.y;
        As[lc + 2][lr] = av.z; As[lc + 3][lr] = av.w;
        Bs[lc + 0][lr] = bv.x; Bs[lc + 1][lr] = bv.y;
        Bs[lc + 2][lr] = bv.z; Bs[lc + 3][lr] = bv.w;
        __syncthreads();

        uint32_t a[4][4], b[4][2];
        #pragma unroll
        for (int mt = 0; mt < 4; mt++) {
            int m0 = mwarp + mt * 16;
            a[mt][0] = __float_as_uint(As[t4][m0 + g]);
            a[mt][1] = __float_as_uint(As[t4][m0 + g + 8]);
            a[mt][2] = __float_as_uint(As[t4 + 4][m0 + g]);
            a[mt][3] = __float_as_uint(As[t4 + 4][m0 + g + 8]);
        }
        #pragma unroll
        for (int nt = 0; nt < 4; nt++) {
            int n0 = nwarp + nt * 8;
            b[nt][0] = __float_as_uint(Bs[t4][n0 + g]);
            b[nt][1] = __float_as_uint(Bs[t4 + 4][n0 + g]);
        }
        #pragma unroll
        for (int mt = 0; mt < 4; mt++)
            #pragma unroll
            for (int nt = 0; nt < 4; nt++)
                mma_tf32(c[mt][nt][0], c[mt][nt][1], c[mt][nt][2], c[mt][nt][3],
                         a[mt][0], a[mt][1], a[mt][2], a[mt][3],
                         b[nt][0], b[nt][1]);
    }

    // epilogue: d2 = xi2 + xj2 - 2G, clamp, store (row-pair float2), track max
    float xj2A[4], xj2B[4];
    #pragma unroll
    for (int nt = 0; nt < 4; nt++) {
        int cA = jb + nwarp + nt * 8 + 2 * t4;
        xj2A[nt] = __ldg(g_x2 + cA);
        xj2B[nt] = __ldg(g_x2 + cA + 1);
    }
    float lmax = 0.0f;
    #pragma unroll
    for (int mt = 0; mt < 4; mt++) {
        int r0 = ib + mwarp + mt * 16 + g;
        int r1 = r0 + 8;
        float xi2a = __ldg(g_x2 + r0);
        float xi2b = __ldg(g_x2 + r1);
        #pragma unroll
        for (int nt = 0; nt < 4; nt++) {
            int cA = jb + nwarp + nt * 8 + 2 * t4;
            float d00 = fmaxf(xi2a + xj2A[nt] - 2.0f * c[mt][nt][0], 1e-12f);
            float d01 = fmaxf(xi2a + xj2B[nt] - 2.0f * c[mt][nt][1], 1e-12f);
            float d10 = fmaxf(xi2b + xj2A[nt] - 2.0f * c[mt][nt][2], 1e-12f);
            float d11 = fmaxf(xi2b + xj2B[nt] - 2.0f * c[mt][nt][3], 1e-12f);
            lmax = fmaxf(lmax, fmaxf(fmaxf(d00, d01), fmaxf(d10, d11)));
            float2 s0 = { d00, d01 };
            float2 s1 = { d10, d11 };
            *(float2*)(g_d2 + (size_t)r0 * NN + cA) = s0;
            *(float2*)(g_d2 + (size_t)r1 * NN + cA) = s1;
        }
    }
    #pragma unroll
    for (int o = 16; o; o >>= 1)
        lmax = fmaxf(lmax, __shfl_xor_sync(0xffffffffu, lmax, o));
    if (lane == 0) redmax[w] = lmax;
    __syncthreads();
    if (t == 0) {
        float m = redmax[0];
        #pragma unroll
        for (int wgi = 1; wgi < 8; wgi++) m = fmaxf(m, redmax[wgi]);
        atomicMax(&g_mdbits, __float_as_int(m));
    }
}

// ---------------- alpha pass (64 j per block, f32x2, partial over i) ----------------
__global__ __launch_bounds__(256, 4) void k_alpha(const float* __restrict__ x,
                                                  const float* __restrict__ r0p) {
    extern __shared__ float sm[];
    float* Xi  = sm;                 // 64*128
    float* ws  = Xi + 64 * PP;       // 64*64
    float* red = ws + 64 * 64;       // 8*64
    int jb  = blockIdx.x * 64;
    int sid = blockIdx.y;
    int t   = threadIdx.x;
    int jj = t & 31, grp = t >> 5;

    float md     = sqrtf(__int_as_float(g_mdbits));
    float r0e    = fminf(__ldg(r0p), md);
    float rr     = r0e * r0e;
    float inv_rr = 1.0f / rr;

    ull accP[2][8];
    #pragma unroll
    for (int h = 0; h < 2; h++)
        #pragma unroll
        for (int q = 0; q < 8; q++) accP[h][q] = 0ull;
    float sa0 = 0.0f, sa1 = 0.0f;

    const float4* x4g = (const float4*)x;
    int ibeg = sid * CHA, iend = ibeg + CHA;
    for (int ib = ibeg; ib < iend; ib += 64) {
        // Xi tile fill (LDG latency overlaps with weight phase via scoreboard)
        #pragma unroll
        for (int u = 0; u < 8; u++) {
            int idx = t + u * 256;
            ((float4*)Xi)[idx] = x4g[ib * 32 + idx];
        }
        // weight phase (independent of Xi)
        #pragma unroll
        for (int s = 0; s < 8; s++) {
            int il = grp * 8 + s;
            size_t base = (size_t)(ib + il) * NN + jb + jj;
            float d0 = g_d2[base];
            float d1 = g_d2[base + 32];
            float w0 = 0.0f, w1 = 0.0f;
            if (d0 < rr) { float b = 1.0f - d0 * inv_rr; w0 = b * b * b; }
            if (d1 < rr) { float b = 1.0f - d1 * inv_rr; w1 = b * b * b; }
            ws[il * 64 + jj]      = w0;
            ws[il * 64 + 32 + jj] = w1;
            sa0 += w0; sa1 += w1;
        }
        __syncthreads();
        const ulonglong2* Xu = (const ulonglong2*)Xi;
        #pragma unroll 2
        for (int i = 0; i < 64; i++) {
            float w0 = ws[i * 64 + jj];
            float w1 = ws[i * 64 + 32 + jj];
            ull w0p = pack2(w0, w0);
            ull w1p = pack2(w1, w1);
            ulonglong2 q0 = Xu[i * 32 + grp * 4 + 0];
            ulonglong2 q1 = Xu[i * 32 + grp * 4 + 1];
            ulonglong2 q2 = Xu[i * 32 + grp * 4 + 2];
            ulonglong2 q3 = Xu[i * 32 + grp * 4 + 3];
            ull xp[8] = { q0.x, q0.y, q1.x, q1.y, q2.x, q2.y, q3.x, q3.y };
            #pragma unroll
            for (int q = 0; q < 8; q++) {
                fma2(accP[0][q], w0p, xp[q]);
                fma2(accP[1][q], w1p, xp[q]);
            }
        }
        __syncthreads();
    }

    red[grp * 64 + jj]      = sa0;
    red[grp * 64 + 32 + jj] = sa1;
    __syncthreads();
    if (t < 64) {
        float s2 = 0.0f;
        #pragma unroll
        for (int g = 0; g < 8; g++) s2 += red[g * 64 + t];
        g_saP[sid * NN + jb + t] = s2;
    }
    #pragma unroll
    for (int h = 0; h < 2; h++) {
        int j = jb + h * 32 + jj;
        float* dst = g_muP + ((size_t)sid * NN + j) * PP + grp * 16;
        #pragma unroll
        for (int q = 0; q < 8; q++)
            *(float2*)(dst + 2 * q) = unpack2(accP[h][q]);
    }
}

// ---------------- finalize mu; U = x - mu, ||U||^2, <y,U> ----------------
__global__ void k_U(const float* __restrict__ x) {
    int row = blockIdx.x;
    int p   = threadIdx.x;  // 128
    float xv = x[(size_t)row * PP + p];

    float num = 0.0f, den = 0.0f;
    #pragma unroll
    for (int s = 0; s < ASPLIT; s++) {
        num += g_muP[((size_t)s * NN + row) * PP + p];
        den += g_saP[s * NN + row];
    }
    float m = (den > 0.0f) ? num / den : xv;   // NaN-guard fallback to y

    float u = xv - m;
    g_U[(size_t)row * PP + p] = u;
    float a = u * u, b = xv * u;
    #pragma unroll
    for (int o = 16; o; o >>= 1) {
        a += __shfl_xor_sync(0xffffffffu, a, o);
        b += __shfl_xor_sync(0xffffffffu, b, o);
    }
    __shared__ float ra[4], rb[4];
    if ((p & 31) == 0) { ra[p >> 5] = a; rb[p >> 5] = b; }
    __syncthreads();
    if (p == 0) {
        g_un2[row] = ra[0] + ra[1] + ra[2] + ra[3];
        g_yU[row]  = rb[0] + rb[1] + rb[2] + rb[3];
    }
}

// ---------------- weight2 ----------------
__device__ __forceinline__ float wfun2(float d, float r) {
    if (d < 0.5f * r) return 1.0f;
    if (d >= r) return 0.0f;
    float tq = (2.0f * d - r) / r;
    float b  = 1.0f - tq * tq;
    return b * b * b;
}

// ---------------- beta pass: ps AND eZ via tf32 mma ----------------
__global__ __launch_bounds__(256, 3) void k_beta(const float* __restrict__ x,
                                                 const float* __restrict__ r1p,
                                                 const float* __restrict__ r2p) {
    extern __shared__ float sm[];
    float* Us  = sm;                   // 64*132
    float* Xi  = Us + 64 * 132;        // 32*132 [i][k]; reused as XiT[128][33] after transpose
    float* ws  = Xi + 32 * 132;        // 64*33  (ws[j][i], tf32-rounded)
    float* psb = ws + 64 * 33;         // 32*66 (ps tile buffer)
    float* red = psb + 32 * 66;        // 8*64
    int jb  = blockIdx.x * 64;
    int sid = blockIdx.y;
    int t   = threadIdx.x;
    int jj = t & 31, grp = t >> 5;
    int lane = t & 31, w = t >> 5;
    int g = lane >> 2, t4 = lane & 3;
    int pmb = (w & 1) * 16;           // ps warp i-tile base
    int pnw = (w >> 1) * 16;          // ps warp j base (two n-tiles pnw, pnw+8)
    int mj  = (w >> 1) * 16;          // eZ warp j-tile base (0,16,32,48)
    int nh  = (w & 1) * 64;           // eZ warp p-half base (0,64)

    float md  = sqrtf(__int_as_float(g_mdbits));
    float r1e = fminf(__ldg(r1p), md);
    float r2e = fminf(__ldg(r2p), md);

    #pragma unroll
    for (int u = 0; u < 32; u++) {
        int idx = t + u * 256;                   // 0..8191
        int r = idx >> 7, c2 = idx & 127;
        Us[r * 132 + c2] = g_U[(size_t)(jb + r) * PP + c2];
    }
    __syncthreads();

    float un2_0 = g_un2[jb + jj],      yu0 = g_yU[jb + jj];
    float un2_1 = g_un2[jb + 32 + jj], yu1 = g_yU[jb + 32 + jj];

    float c[8][4];                    // eZ accumulators, live across i-loop
    #pragma unroll
    for (int nt = 0; nt < 8; nt++)
        #pragma unroll
        for (int q = 0; q < 4; q++) c[nt][q] = 0.0f;
    float sb0 = 0.0f, sb1 = 0.0f;

    const float4* x4g = (const float4*)x;

    int ibeg = sid * BCH;
    int iend = min(NN, ibeg + BCH);
    for (int ib = ibeg; ib < iend; ib += 32) {
        // Xi tile fill (32 rows, padded stride 132)
        #pragma unroll
        for (int u = 0; u < 4; u++) {
            int idx = t + u * 256;         // float4 index 0..1023
            int r = idx >> 5, c4 = idx & 31;
            *(float4*)(Xi + r * 132 + c4 * 4) = x4g[ib * 32 + idx];
        }
        // d2 into registers (independent loads; overlap Xi fill latency)
        float d0r[4], d1r[4];
        #pragma unroll
        for (int s = 0; s < 4; s++) {
            size_t base = (size_t)(ib + grp * 4 + s) * NN + jb + jj;
            d0r[s] = g_d2[base];
            d1r[s] = g_d2[base + 32];
        }
        __syncthreads();

        // ps[i][j] = sum_k Xi[i][k] * U[j][k]  via tf32 mma (warp: m16 x n16, K=128)
        float cc[2][4];
        #pragma unroll
        for (int nt = 0; nt < 2; nt++)
            #pragma unroll
            for (int q = 0; q < 4; q++) cc[nt][q] = 0.0f;
        #pragma unroll
        for (int k0 = 0; k0 < PP; k0 += 8) {
            uint32_t a0 = __float_as_uint(Xi[(pmb + g) * 132 + k0 + t4]);
            uint32_t a1 = __float_as_uint(Xi[(pmb + g + 8) * 132 + k0 + t4]);
            uint32_t a2 = __float_as_uint(Xi[(pmb + g) * 132 + k0 + t4 + 4]);
            uint32_t a3 = __float_as_uint(Xi[(pmb + g + 8) * 132 + k0 + t4 + 4]);
            #pragma unroll
            for (int nt = 0; nt < 2; nt++) {
                int n0 = pnw + nt * 8;
                uint32_t b0 = __float_as_uint(Us[(n0 + g) * 132 + k0 + t4]);
                uint32_t b1 = __float_as_uint(Us[(n0 + g) * 132 + k0 + t4 + 4]);
                mma_tf32(cc[nt][0], cc[nt][1], cc[nt][2], cc[nt][3],
                         a0, a1, a2, a3, b0, b1);
            }
        }
        // spill ps fragments to smem
        #pragma unroll
        for (int nt = 0; nt < 2; nt++) {
            int n0 = pnw + nt * 8;
            float2 p01 = { cc[nt][0], cc[nt][1] };
            float2 p23 = { cc[nt][2], cc[nt][3] };
            *(float2*)(psb + (pmb + g) * 66 + n0 + 2 * t4)     = p01;
            *(float2*)(psb + (pmb + g + 8) * 66 + n0 + 2 * t4) = p23;
        }
        __syncthreads();

        // weights (tf32-rounded; stored [j][i] for eZ mma A-fragments)
        #pragma unroll
        for (int s = 0; s < 4; s++) {
            int il = grp * 4 + s;
            float d0 = d0r[s];
            float d1 = d1r[s];
            float ps0 = psb[il * 66 + jj];
            float ps1 = psb[il * 66 + 32 + jj];
            float psv0 = ps0 - yu0;
            float psv1 = ps1 - yu1;
            float du2_0 = fmaxf(psv0 * psv0 * un2_0, 1e-6f);
            float du2_1 = fmaxf(psv1 * psv1 * un2_1, 1e-6f);
            float dv0 = sqrtf(fmaxf(d0 - du2_0, 1e-6f));
            float dv1 = sqrtf(fmaxf(d1 - du2_1, 1e-6f));
            float du0 = sqrtf(du2_0);
            float du1 = sqrtf(du2_1);
            float w0 = wfun2(dv0, r1e) * wfun2(du0, r2e);
            float w1 = wfun2(dv1, r1e) * wfun2(du1, r2e);
            w0 = tf32_round(w0);
            w1 = tf32_round(w1);
            ws[jj * 33 + il]        = w0;
            ws[(jj + 32) * 33 + il] = w1;
            sb0 += w0; sb1 += w1;
        }
        // transpose Xi [i][k] -> XiT [k][i] (register-staged, same buffer)
        float tr[16];
        #pragma unroll
        for (int u = 0; u < 16; u++) {
            int idx = t + u * 256;       // 0..4095
            int i = idx >> 7, p = idx & 127;
            tr[u] = Xi[i * 132 + p];
        }
        __syncthreads();                 // all Xi reads done; ws visible
        #pragma unroll
        for (int u = 0; u < 16; u++) {
            int idx = t + u * 256;
            int i = idx >> 7, p = idx & 127;
            Xi[p * 33 + i] = tr[u];      // XiT layout
        }
        __syncthreads();                 // XiT ready

        // eZ mma: eZ[j][p] += ws[j][i] * XiT[p][i]  (4 k-steps of 8 i)
        #pragma unroll
        for (int k0 = 0; k0 < 32; k0 += 8) {
            uint32_t a0 = __float_as_uint(ws[(mj + g) * 33 + k0 + t4]);
            uint32_t a1 = __float_as_uint(ws[(mj + g + 8) * 33 + k0 + t4]);
            uint32_t a2 = __float_as_uint(ws[(mj + g) * 33 + k0 + t4 + 4]);
            uint32_t a3 = __float_as_uint(ws[(mj + g + 8) * 33 + k0 + t4 + 4]);
            #pragma unroll
            for (int nt = 0; nt < 8; nt++) {
                int n0 = nh + nt * 8;
                uint32_t b0 = __float_as_uint(Xi[(n0 + g) * 33 + k0 + t4]);
                uint32_t b1 = __float_as_uint(Xi[(n0 + g) * 33 + k0 + t4 + 4]);
                mma_tf32(c[nt][0], c[nt][1], c[nt][2], c[nt][3],
                         a0, a1, a2, a3, b0, b1);
            }
        }
        __syncthreads();                 // before next tile overwrites Xi/ws
    }

    red[grp * 64 + jj]      = sb0;
    red[grp * 64 + 32 + jj] = sb1;
    __syncthreads();
    if (t < 64) {
        float s2 = 0.0f;
        #pragma unroll
        for (int gg = 0; gg < 8; gg++) s2 += red[gg * 64 + t];
        g_sbP[sid * NN + jb + t] = s2;
    }
    // eZ fragment store: rows j = jb+mj+g (+8), cols p = nh + nt*8 + 2*t4
    #pragma unroll
    for (int nt = 0; nt < 8; nt++) {
        int p  = nh + nt * 8 + 2 * t4;
        int j0 = jb + mj + g;
        int j1 = j0 + 8;
        float2 s0 = { c[nt][0], c[nt][1] };
        float2 s1 = { c[nt][2], c[nt][3] };
        *(float2*)(g_eZP + ((size_t)sid * NN + j0) * PP + p) = s0;
        *(float2*)(g_eZP + ((size_t)sid * NN + j1) * PP + p) = s1;
    }
}

// ---------------- fused eZ-finalize + MLP + MSE loss ----------------
__device__ __forceinline__ float gelu_exact(float v) {
    return 0.5f * v * (1.0f + erff(v * 0.70710678118654752f));
}

__global__ void k_mlp(const float* __restrict__ x,
                      const float* __restrict__ We1, const float* __restrict__ be1,
                      const float* __restrict__ We2, const float* __restrict__ be2,
                      const float* __restrict__ Wd1, const float* __restrict__ bd1,
                      const float* __restrict__ Wd2, const float* __restrict__ bd2,
                      float* __restrict__ out) {
    __shared__ float We1s[32 * 129];
    __shared__ float Wd2s[128 * 33];
    __shared__ float We2s[32 * 33];
    __shared__ float Wd1s[32 * 33];
    __shared__ float be1s[32], be2s[32], bd1s[32], bd2s[128];
    int t = threadIdx.x;
    for (int idx = t; idx < 32 * 128; idx += 256)
        We1s[(idx >> 7) * 129 + (idx & 127)] = We1[idx];
    for (int idx = t; idx < 128 * 32; idx += 256)
        Wd2s[(idx >> 5) * 33 + (idx & 31)] = Wd2[idx];
    for (int idx = t; idx < 32 * 32; idx += 256) {
        We2s[(idx >> 5) * 33 + (idx & 31)] = We2[idx];
        Wd1s[(idx >> 5) * 33 + (idx & 31)] = Wd1[idx];
    }
    if (t < 32) { be1s[t] = be1[t]; be2s[t] = be2[t]; bd1s[t] = bd1[t]; }
    if (t < 128) bd2s[t] = bd2[t];
    __syncthreads();

    int lane = t & 31;
    int warp = t >> 5;
    int gw = blockIdx.x * 8 + warp;
    int nw = gridDim.x * 8;
    float part = 0.0f;

    for (int row = gw; row < NN; row += nw) {
        float den = 0.0f;
        #pragma unroll
        for (int s = 0; s < BSPLIT; s++) den += g_sbP[s * NN + row];
        float y0 = 0.0f, y1 = 0.0f, y2 = 0.0f, y3 = 0.0f;
        #pragma unroll
        for (int s = 0; s < BSPLIT; s++) {
            const float* pr = g_eZP + ((size_t)s * NN + row) * PP;
            y0 += pr[lane];       y1 += pr[32 + lane];
            y2 += pr[64 + lane];  y3 += pr[96 + lane];
        }
        if (den > 0.0f) {
            float inv = 1.0f / den;
            y0 *= inv; y1 *= inv; y2 *= inv; y3 *= inv;
        } else {
            const float* xr = x + (size_t)row * PP;
            y0 = xr[lane];      y1 = xr[32 + lane];
            y2 = xr[64 + lane]; y3 = xr[96 + lane];
        }

        float h = be1s[lane];
        const float* wrow = We1s + lane * 129;
        #pragma unroll 8
        for (int k = 0; k < 32; k++) {
            h = fmaf(__shfl_sync(0xffffffffu, y0, k), wrow[k], h);
            h = fmaf(__shfl_sync(0xffffffffu, y1, k), wrow[32 + k], h);
            h = fmaf(__shfl_sync(0xffffffffu, y2, k), wrow[64 + k], h);
            h = fmaf(__shfl_sync(0xffffffffu, y3, k), wrow[96 + k], h);
        }
        h = gelu_exact(h);

        float z = be2s[lane];
        const float* w2row = We2s + lane * 33;
        #pragma unroll
        for (int m = 0; m < 32; m++)
            z = fmaf(__shfl_sync(0xffffffffu, h, m), w2row[m], z);

        float h2 = bd1s[lane];
        const float* w3row = Wd1s + lane * 33;
        #pragma unroll
        for (int m = 0; m < 32; m++)
            h2 = fmaf(__shfl_sync(0xffffffffu, z, m), w3row[m], h2);
        h2 = gelu_exact(h2);

        float xh[4];
        #pragma unroll
        for (int q = 0; q < 4; q++) xh[q] = bd2s[q * 32 + lane];
        #pragma unroll
        for (int m = 0; m < 32; m++) {
            float hm = __shfl_sync(0xffffffffu, h2, m);
            #pragma unroll
            for (int q = 0; q < 4; q++)
                xh[q] = fmaf(hm, Wd2s[(q * 32 + lane) * 33 + m], xh[q]);
        }
        #pragma unroll
        for (int q = 0; q < 4; q++) {
            int p = q * 32 + lane;
            float s   = 1.0f / (1.0f + expf(-xh[q]));
            float dlt = x[(size_t)row * PP + p] - s;
            part = fmaf(dlt, dlt, part);
        }
    }
    #pragma unroll
    for (int o = 16; o; o >>= 1) part += __shfl_xor_sync(0xffffffffu, part, o);
    if (lane == 0) atomicAdd(out, part * (1.0f / ((float)NN * (float)PP)));
}

// ---------------- launch ----------------
extern "C" void kernel_launch(void* const* d_in, const int* in_sizes, int n_in,
                              void* d_out, int out_size) {
    const float* x   = (const float*)d_in[0];
    const float* r0  = (const float*)d_in[1];
    const float* r1  = (const float*)d_in[2];
    const float* r2  = (const float*)d_in[3];
    const float* We1 = (const float*)d_in[4];
    const float* be1 = (const float*)d_in[5];
    const float* We2 = (const float*)d_in[6];
    const float* be2 = (const float*)d_in[7];
    const float* Wd1 = (const float*)d_in[8];
    const float* bd1 = (const float*)d_in[9];
    const float* Wd2 = (const float*)d_in[10];
    const float* bd2 = (const float*)d_in[11];
    float* out = (float*)d_out;

    size_t smA = (size_t)(64 * PP + 64 * 64 + 8 * 64) * sizeof(float);            // 51200
    size_t smB = (size_t)(64 * 132 + 32 * 132 + 64 * 33 + 32 * 66 + 8 * 64) * sizeof(float); // 69632
    cudaFuncSetAttribute(k_alpha, cudaFuncAttributeMaxDynamicSharedMemorySize, (int)smA);
    cudaFuncSetAttribute(k_beta,  cudaFuncAttributeMaxDynamicSharedMemorySize, (int)smB);

    k_zero<<<1, 1>>>(out);
    k_x2<<<NN, 32>>>(x);
    k_gram<<<dim3(32, 32), 256>>>(x);
    k_alpha<<<dim3(64, ASPLIT), 256, smA>>>(x, r0);
    k_U<<<NN, 128>>>(x);
    k_beta<<<dim3(64, BSPLIT), 256, smB>>>(x, r1, r2);
    k_mlp<<<128, 256>>>(x, We1, be1, We2, be2, Wd1, bd1, Wd2, bd2, out);
}

// round 17
// speedup vs baseline: 1.6574x; 1.0647x over previous
#include <cuda_runtime.h>
#include <math.h>
#include <stdint.h>

#define NN 4096
#define PP 128
#define LL 32
#define ASPLIT 8
#define BSPLIT 6
#define CHA (NN / ASPLIT)   // 512
#define BCH 704             // beta split size (5*704 + 576 = 4096)

// ---------------- scratch (device globals; no allocation) ----------------
__device__ float g_x2[NN];
__device__ float g_d2[(size_t)NN * NN];    // clamped squared distances (64 MB)
__device__ int   g_mdbits;                 // atomicMax of d2c as ordered int
__device__ float g_muP[ASPLIT * NN * PP];  // unnormalized mu partials
__device__ float g_saP[ASPLIT * NN];       // alpha weight-sum partials
__device__ float g_eZP[BSPLIT * NN * PP];  // unnormalized eZ partials
__device__ float g_sbP[BSPLIT * NN];       // beta weight-sum partials
__device__ float g_U[NN * PP];
__device__ float g_un2[NN];
__device__ float g_yU[NN];

// ---------------- f32x2 packed helpers ----------------
typedef unsigned long long ull;

__device__ __forceinline__ void fma2(ull& d, ull a, ull b) {
    asm("fma.rn.f32x2 %0, %1, %2, %0;" : "+l"(d) : "l"(a), "l"(b));
}
__device__ __forceinline__ ull pack2(float lo, float hi) {
    ull r;
    asm("mov.b64 %0, {%1, %2};" : "=l"(r) : "f"(lo), "f"(hi));
    return r;
}
__device__ __forceinline__ float2 unpack2(ull v) {
    float2 r;
    asm("mov.b64 {%0, %1}, %2;" : "=f"(r.x), "=f"(r.y) : "l"(v));
    return r;
}

// ---------------- tf32 helpers ----------------
__device__ __forceinline__ void mma_tf32(float& c0, float& c1, float& c2, float& c3,
                                         uint32_t a0, uint32_t a1, uint32_t a2, uint32_t a3,
                                         uint32_t b0, uint32_t b1) {
    asm("mma.sync.aligned.m16n8k8.row.col.f32.tf32.tf32.f32 "
        "{%0,%1,%2,%3}, {%4,%5,%6,%7}, {%8,%9}, {%0,%1,%2,%3};"
        : "+f"(c0), "+f"(c1), "+f"(c2), "+f"(c3)
        : "r"(a0), "r"(a1), "r"(a2), "r"(a3), "r"(b0), "r"(b1));
}
__device__ __forceinline__ float tf32_round(float v) {
    uint32_t u;
    asm("cvt.rna.tf32.f32 %0, %1;" : "=r"(u) : "f"(v));
    return __uint_as_float(u);
}

// ---------------- tiny init ----------------
__global__ void k_zero(float* out) {
    g_mdbits = 0;
    out[0] = 0.0f;
}

// ---------------- x2[i] = ||x_i||^2 ----------------
__global__ void k_x2(const float* __restrict__ x) {
    int row  = blockIdx.x;
    int lane = threadIdx.x;              // 32 threads
    const float4* x4 = (const float4*)x;
    float4 v = x4[row * 32 + lane];
    float s = v.x * v.x + v.y * v.y + v.z * v.z + v.w * v.w;
    #pragma unroll
    for (int o = 16; o; o >>= 1) s += __shfl_xor_sync(0xffffffffu, s, o);
    if (lane == 0) g_x2[row] = s;
}

// ---------------- Gram / dist^2 via tf32 mma (128x128 tile, full grid) ----------------
__global__ __launch_bounds__(256, 2) void k_gram(const float* __restrict__ x) {
    __shared__ float As[8][140];   // As[kk][i]  (k-major)
    __shared__ float Bs[8][140];   // Bs[kk][j]
    __shared__ float redmax[8];
    int jb = blockIdx.x * 128, ib = blockIdx.y * 128;
    int t    = threadIdx.x;
    int w    = t >> 5;
    int lane = t & 31;
    int g    = lane >> 2;           // 0..7
    int t4   = lane & 3;            // 0..3
    int mwarp = (w & 1) * 64;       // warp covers m 64, n 32
    int nwarp = (w >> 1) * 32;

    float c[4][4][4];               // [mt][nt][{c0..c3}]
    #pragma unroll
    for (int mt = 0; mt < 4; mt++)
        #pragma unroll
        for (int nt = 0; nt < 4; nt++)
            #pragma unroll
            for (int q = 0; q < 4; q++) c[mt][nt][q] = 0.0f;

    int lr = t >> 1, lc = (t & 1) * 4;
    for (int k0 = 0; k0 < PP; k0 += 8) {
        float4 av = *(const float4*)(x + (size_t)(ib + lr) * PP + k0 + lc);
        float4 bv = *(const float4*)(x + (size_t)(jb + lr) * PP + k0 + lc);
        __syncthreads();
        As[lc + 0][lr] = av.x; As[lc + 1][lr] = av.y;
        As[lc + 2][lr] = av.z; As[lc + 3][lr] = av.w;
        Bs[lc + 0][lr] = bv.x; Bs[lc + 1][lr] = bv.y;
        Bs[lc + 2][lr] = bv.z; Bs[lc + 3][lr] = bv.w;
        __syncthreads();

        uint32_t a[4][4], b[4][2];
        #pragma unroll
        for (int mt = 0; mt < 4; mt++) {
            int m0 = mwarp + mt * 16;
            a[mt][0] = __float_as_uint(As[t4][m0 + g]);
            a[mt][1] = __float_as_uint(As[t4][m0 + g + 8]);
            a[mt][2] = __float_as_uint(As[t4 + 4][m0 + g]);
            a[mt][3] = __float_as_uint(As[t4 + 4][m0 + g + 8]);
        }
        #pragma unroll
        for (int nt = 0; nt < 4; nt++) {
            int n0 = nwarp + nt * 8;
            b[nt][0] = __float_as_uint(Bs[t4][n0 + g]);
            b[nt][1] = __float_as_uint(Bs[t4 + 4][n0 + g]);
        }
        #pragma unroll
        for (int mt = 0; mt < 4; mt++)
            #pragma unroll
            for (int nt = 0; nt < 4; nt++)
                mma_tf32(c[mt][nt][0], c[mt][nt][1], c[mt][nt][2], c[mt][nt][3],
                         a[mt][0], a[mt][1], a[mt][2], a[mt][3],
                         b[nt][0], b[nt][1]);
    }

    // epilogue: d2 = xi2 + xj2 - 2G, clamp, store (row-pair float2), track max
    float xj2A[4], xj2B[4];
    #pragma unroll
    for (int nt = 0; nt < 4; nt++) {
        int cA = jb + nwarp + nt * 8 + 2 * t4;
        xj2A[nt] = __ldg(g_x2 + cA);
        xj2B[nt] = __ldg(g_x2 + cA + 1);
    }
    float lmax = 0.0f;
    #pragma unroll
    for (int mt = 0; mt < 4; mt++) {
        int r0 = ib + mwarp + mt * 16 + g;
        int r1 = r0 + 8;
        float xi2a = __ldg(g_x2 + r0);
        float xi2b = __ldg(g_x2 + r1);
        #pragma unroll
        for (int nt = 0; nt < 4; nt++) {
            int cA = jb + nwarp + nt * 8 + 2 * t4;
            float d00 = fmaxf(xi2a + xj2A[nt] - 2.0f * c[mt][nt][0], 1e-12f);
            float d01 = fmaxf(xi2a + xj2B[nt] - 2.0f * c[mt][nt][1], 1e-12f);
            float d10 = fmaxf(xi2b + xj2A[nt] - 2.0f * c[mt][nt][2], 1e-12f);
            float d11 = fmaxf(xi2b + xj2B[nt] - 2.0f * c[mt][nt][3], 1e-12f);
            lmax = fmaxf(lmax, fmaxf(fmaxf(d00, d01), fmaxf(d10, d11)));
            float2 s0 = { d00, d01 };
            float2 s1 = { d10, d11 };
            *(float2*)(g_d2 + (size_t)r0 * NN + cA) = s0;
            *(float2*)(g_d2 + (size_t)r1 * NN + cA) = s1;
        }
    }
    #pragma unroll
    for (int o = 16; o; o >>= 1)
        lmax = fmaxf(lmax, __shfl_xor_sync(0xffffffffu, lmax, o));
    if (lane == 0) redmax[w] = lmax;
    __syncthreads();
    if (t == 0) {
        float m = redmax[0];
        #pragma unroll
        for (int wgi = 1; wgi < 8; wgi++) m = fmaxf(m, redmax[wgi]);
        atomicMax(&g_mdbits, __float_as_int(m));
    }
}

// ---------------- alpha pass: mu via tf32 mma, 1-tile software pipeline ----------------
__global__ __launch_bounds__(256, 2) void k_alpha(const float* __restrict__ x,
                                                  const float* __restrict__ r0p) {
    extern __shared__ float sm[];
    float* XiT = sm;                  // 128 * 33 (x transposed: XiT[p][i])
    float* ws  = XiT + 128 * 33;      // 64 * 33  (ws[j][i], tf32-rounded)
    float* red = ws + 64 * 33;        // 8 * 64
    int jb  = blockIdx.x * 64;
    int sid = blockIdx.y;
    int t   = threadIdx.x;
    int jj = t & 31, grp = t >> 5;
    int lane = t & 31, w = t >> 5;
    int g = lane >> 2, t4 = lane & 3;
    int mj = (w >> 1) * 16;           // warp j-tile base (0,16,32,48)
    int nh = (w & 1) * 64;            // warp p-half base (0,64); 8 n-tiles of 8

    float md     = sqrtf(__int_as_float(g_mdbits));
    float r0e    = fminf(__ldg(r0p), md);
    float rr     = r0e * r0e;
    float inv_rr = 1.0f / rr;

    float c[8][4];                    // mu accumulators, live across i-loop
    #pragma unroll
    for (int nt = 0; nt < 8; nt++)
        #pragma unroll
        for (int q = 0; q < 4; q++) c[nt][q] = 0.0f;
    float sa0 = 0.0f, sa1 = 0.0f;

    int ibeg = sid * CHA, iend = ibeg + CHA;

    // ---- prologue: prefetch tile 0 (x and d2) into registers ----
    float xr[16], dr0[4], dr1[4];
    #pragma unroll
    for (int u = 0; u < 16; u++) {
        int idx = t + u * 256;        // 0..4095
        int i = idx >> 7, p = idx & 127;
        xr[u] = x[(size_t)(ibeg + i) * PP + p];
    }
    #pragma unroll
    for (int s = 0; s < 4; s++) {
        size_t base = (size_t)(ibeg + grp * 4 + s) * NN + jb + jj;
        dr0[s] = g_d2[base];
        dr1[s] = g_d2[base + 32];
    }

    for (int ib = ibeg; ib < iend; ib += 32) {
        // drain staged registers to smem (no memory wait)
        #pragma unroll
        for (int u = 0; u < 16; u++) {
            int idx = t + u * 256;
            int i = idx >> 7, p = idx & 127;
            XiT[p * 33 + i] = xr[u];
        }
        #pragma unroll
        for (int s = 0; s < 4; s++) {
            int il = grp * 4 + s;
            float d0 = dr0[s], d1 = dr1[s];
            float w0 = 0.0f, w1 = 0.0f;
            if (d0 < rr) { float b = 1.0f - d0 * inv_rr; w0 = b * b * b; }
            if (d1 < rr) { float b = 1.0f - d1 * inv_rr; w1 = b * b * b; }
            w0 = tf32_round(w0);
            w1 = tf32_round(w1);
            ws[jj * 33 + il]        = w0;
            ws[(jj + 32) * 33 + il] = w1;
            sa0 += w0; sa1 += w1;
        }
        __syncthreads();
        // prefetch next tile while mma runs
        int inext = ib + 32;
        if (inext < iend) {
            #pragma unroll
            for (int u = 0; u < 16; u++) {
                int idx = t + u * 256;
                int i = idx >> 7, p = idx & 127;
                xr[u] = x[(size_t)(inext + i) * PP + p];
            }
            #pragma unroll
            for (int s = 0; s < 4; s++) {
                size_t base = (size_t)(inext + grp * 4 + s) * NN + jb + jj;
                dr0[s] = g_d2[base];
                dr1[s] = g_d2[base + 32];
            }
        }
        // mma phase: mu[j][p] += ws[j][i] * XiT[p][i]  (4 k-steps of 8 i)
        #pragma unroll
        for (int k0 = 0; k0 < 32; k0 += 8) {
            uint32_t a0 = __float_as_uint(ws[(mj + g) * 33 + k0 + t4]);
            uint32_t a1 = __float_as_uint(ws[(mj + g + 8) * 33 + k0 + t4]);
            uint32_t a2 = __float_as_uint(ws[(mj + g) * 33 + k0 + t4 + 4]);
            uint32_t a3 = __float_as_uint(ws[(mj + g + 8) * 33 + k0 + t4 + 4]);
            #pragma unroll
            for (int nt = 0; nt < 8; nt++) {
                int n0 = nh + nt * 8;
                uint32_t b0 = __float_as_uint(XiT[(n0 + g) * 33 + k0 + t4]);
                uint32_t b1 = __float_as_uint(XiT[(n0 + g) * 33 + k0 + t4 + 4]);
                mma_tf32(c[nt][0], c[nt][1], c[nt][2], c[nt][3],
                         a0, a1, a2, a3, b0, b1);
            }
        }
        __syncthreads();
    }

    // sa reduce across groups
    red[grp * 64 + jj]      = sa0;
    red[grp * 64 + 32 + jj] = sa1;
    __syncthreads();
    if (t < 64) {
        float s2 = 0.0f;
        #pragma unroll
        for (int gg = 0; gg < 8; gg++) s2 += red[gg * 64 + t];
        g_saP[sid * NN + jb + t] = s2;
    }
    // mu fragment store: rows j = jb+mj+g (+8), cols p = nh + nt*8 + 2*t4
    #pragma unroll
    for (int nt = 0; nt < 8; nt++) {
        int p  = nh + nt * 8 + 2 * t4;
        int j0 = jb + mj + g;
        int j1 = j0 + 8;
        float2 s0 = { c[nt][0], c[nt][1] };
        float2 s1 = { c[nt][2], c[nt][3] };
        *(float2*)(g_muP + ((size_t)sid * NN + j0) * PP + p) = s0;
        *(float2*)(g_muP + ((size_t)sid * NN + j1) * PP + p) = s1;
    }
}

// ---------------- finalize mu; U = x - mu, ||U||^2, <y,U> ----------------
__global__ void k_U(const float* __restrict__ x) {
    int row = blockIdx.x;
    int p   = threadIdx.x;  // 128
    float xv = x[(size_t)row * PP + p];

    float num = 0.0f, den = 0.0f;
    #pragma unroll
    for (int s = 0; s < ASPLIT; s++) {
        num += g_muP[((size_t)s * NN + row) * PP + p];
        den += g_saP[s * NN + row];
    }
    float m = (den > 0.0f) ? num / den : xv;   // NaN-guard fallback to y

    float u = xv - m;
    g_U[(size_t)row * PP + p] = u;
    float a = u * u, b = xv * u;
    #pragma unroll
    for (int o = 16; o; o >>= 1) {
        a += __shfl_xor_sync(0xffffffffu, a, o);
        b += __shfl_xor_sync(0xffffffffu, b, o);
    }
    __shared__ float ra[4], rb[4];
    if ((p & 31) == 0) { ra[p >> 5] = a; rb[p >> 5] = b; }
    __syncthreads();
    if (p == 0) {
        g_un2[row] = ra[0] + ra[1] + ra[2] + ra[3];
        g_yU[row]  = rb[0] + rb[1] + rb[2] + rb[3];
    }
}

// ---------------- weight2 ----------------
__device__ __forceinline__ float wfun2(float d, float r) {
    if (d < 0.5f * r) return 1.0f;
    if (d >= r) return 0.0f;
    float tq = (2.0f * d - r) / r;
    float b  = 1.0f - tq * tq;
    return b * b * b;
}

// ---------------- beta pass: ps AND eZ via tf32 mma ----------------
__global__ __launch_bounds__(256, 3) void k_beta(const float* __restrict__ x,
                                                 const float* __restrict__ r1p,
                                                 const float* __restrict__ r2p) {
    extern __shared__ float sm[];
    float* Us  = sm;                   // 64*132
    float* Xi  = Us + 64 * 132;        // 32*132 [i][k]; reused as XiT[128][33] after transpose
    float* ws  = Xi + 32 * 132;        // 64*33  (ws[j][i], tf32-rounded)
    float* psb = ws + 64 * 33;         // 32*66 (ps tile buffer)
    float* red = psb + 32 * 66;        // 8*64
    int jb  = blockIdx.x * 64;
    int sid = blockIdx.y;
    int t   = threadIdx.x;
    int jj = t & 31, grp = t >> 5;
    int lane = t & 31, w = t >> 5;
    int g = lane >> 2, t4 = lane & 3;
    int pmb = (w & 1) * 16;           // ps warp i-tile base
    int pnw = (w >> 1) * 16;          // ps warp j base (two n-tiles pnw, pnw+8)
    int mj  = (w >> 1) * 16;          // eZ warp j-tile base (0,16,32,48)
    int nh  = (w & 1) * 64;           // eZ warp p-half base (0,64)

    float md  = sqrtf(__int_as_float(g_mdbits));
    float r1e = fminf(__ldg(r1p), md);
    float r2e = fminf(__ldg(r2p), md);

    #pragma unroll
    for (int u = 0; u < 32; u++) {
        int idx = t + u * 256;                   // 0..8191
        int r = idx >> 7, c2 = idx & 127;
        Us[r * 132 + c2] = g_U[(size_t)(jb + r) * PP + c2];
    }
    __syncthreads();

    float un2_0 = g_un2[jb + jj],      yu0 = g_yU[jb + jj];
    float un2_1 = g_un2[jb + 32 + jj], yu1 = g_yU[jb + 32 + jj];

    float c[8][4];                    // eZ accumulators, live across i-loop
    #pragma unroll
    for (int nt = 0; nt < 8; nt++)
        #pragma unroll
        for (int q = 0; q < 4; q++) c[nt][q] = 0.0f;
    float sb0 = 0.0f, sb1 = 0.0f;

    const float4* x4g = (const float4*)x;

    int ibeg = sid * BCH;
    int iend = min(NN, ibeg + BCH);
    for (int ib = ibeg; ib < iend; ib += 32) {
        // Xi tile fill (32 rows, padded stride 132)
        #pragma unroll
        for (int u = 0; u < 4; u++) {
            int idx = t + u * 256;         // float4 index 0..1023
            int r = idx >> 5, c4 = idx & 31;
            *(float4*)(Xi + r * 132 + c4 * 4) = x4g[ib * 32 + idx];
        }
        // d2 into registers (independent loads; overlap Xi fill latency)
        float d0r[4], d1r[4];
        #pragma unroll
        for (int s = 0; s < 4; s++) {
            size_t base = (size_t)(ib + grp * 4 + s) * NN + jb + jj;
            d0r[s] = g_d2[base];
            d1r[s] = g_d2[base + 32];
        }
        __syncthreads();

        // ps[i][j] = sum_k Xi[i][k] * U[j][k]  via tf32 mma (warp: m16 x n16, K=128)
        float cc[2][4];
        #pragma unroll
        for (int nt = 0; nt < 2; nt++)
            #pragma unroll
            for (int q = 0; q < 4; q++) cc[nt][q] = 0.0f;
        #pragma unroll
        for (int k0 = 0; k0 < PP; k0 += 8) {
            uint32_t a0 = __float_as_uint(Xi[(pmb + g) * 132 + k0 + t4]);
            uint32_t a1 = __float_as_uint(Xi[(pmb + g + 8) * 132 + k0 + t4]);
            uint32_t a2 = __float_as_uint(Xi[(pmb + g) * 132 + k0 + t4 + 4]);
            uint32_t a3 = __float_as_uint(Xi[(pmb + g + 8) * 132 + k0 + t4 + 4]);
            #pragma unroll
            for (int nt = 0; nt < 2; nt++) {
                int n0 = pnw + nt * 8;
                uint32_t b0 = __float_as_uint(Us[(n0 + g) * 132 + k0 + t4]);
                uint32_t b1 = __float_as_uint(Us[(n0 + g) * 132 + k0 + t4 + 4]);
                mma_tf32(cc[nt][0], cc[nt][1], cc[nt][2], cc[nt][3],
                         a0, a1, a2, a3, b0, b1);
            }
        }
        // spill ps fragments to smem
        #pragma unroll
        for (int nt = 0; nt < 2; nt++) {
            int n0 = pnw + nt * 8;
            float2 p01 = { cc[nt][0], cc[nt][1] };
            float2 p23 = { cc[nt][2], cc[nt][3] };
            *(float2*)(psb + (pmb + g) * 66 + n0 + 2 * t4)     = p01;
            *(float2*)(psb + (pmb + g + 8) * 66 + n0 + 2 * t4) = p23;
        }
        __syncthreads();

        // weights (tf32-rounded; stored [j][i] for eZ mma A-fragments)
        #pragma unroll
        for (int s = 0; s < 4; s++) {
            int il = grp * 4 + s;
            float d0 = d0r[s];
            float d1 = d1r[s];
            float ps0 = psb[il * 66 + jj];
            float ps1 = psb[il * 66 + 32 + jj];
            float psv0 = ps0 - yu0;
            float psv1 = ps1 - yu1;
            float du2_0 = fmaxf(psv0 * psv0 * un2_0, 1e-6f);
            float du2_1 = fmaxf(psv1 * psv1 * un2_1, 1e-6f);
            float dv0 = sqrtf(fmaxf(d0 - du2_0, 1e-6f));
            float dv1 = sqrtf(fmaxf(d1 - du2_1, 1e-6f));
            float du0 = sqrtf(du2_0);
            float du1 = sqrtf(du2_1);
            float w0 = wfun2(dv0, r1e) * wfun2(du0, r2e);
            float w1 = wfun2(dv1, r1e) * wfun2(du1, r2e);
            w0 = tf32_round(w0);
            w1 = tf32_round(w1);
            ws[jj * 33 + il]        = w0;
            ws[(jj + 32) * 33 + il] = w1;
            sb0 += w0; sb1 += w1;
        }
        // transpose Xi [i][k] -> XiT [k][i] (register-staged, same buffer)
        float tr[16];
        #pragma unroll
        for (int u = 0; u < 16; u++) {
            int idx = t + u * 256;       // 0..4095
            int i = idx >> 7, p = idx & 127;
            tr[u] = Xi[i * 132 + p];
        }
        __syncthreads();                 // all Xi reads done; ws visible
        #pragma unroll
        for (int u = 0; u < 16; u++) {
            int idx = t + u * 256;
            int i = idx >> 7, p = idx & 127;
            Xi[p * 33 + i] = tr[u];      // XiT layout
        }
        __syncthreads();                 // XiT ready

        // eZ mma: eZ[j][p] += ws[j][i] * XiT[p][i]  (4 k-steps of 8 i)
        #pragma unroll
        for (int k0 = 0; k0 < 32; k0 += 8) {
            uint32_t a0 = __float_as_uint(ws[(mj + g) * 33 + k0 + t4]);
            uint32_t a1 = __float_as_uint(ws[(mj + g + 8) * 33 + k0 + t4]);
            uint32_t a2 = __float_as_uint(ws[(mj + g) * 33 + k0 + t4 + 4]);
            uint32_t a3 = __float_as_uint(ws[(mj + g + 8) * 33 + k0 + t4 + 4]);
            #pragma unroll
            for (int nt = 0; nt < 8; nt++) {
                int n0 = nh + nt * 8;
                uint32_t b0 = __float_as_uint(Xi[(n0 + g) * 33 + k0 + t4]);
                uint32_t b1 = __float_as_uint(Xi[(n0 + g) * 33 + k0 + t4 + 4]);
                mma_tf32(c[nt][0], c[nt][1], c[nt][2], c[nt][3],
                         a0, a1, a2, a3, b0, b1);
            }
        }
        __syncthreads();                 // before next tile overwrites Xi/ws
    }

    red[grp * 64 + jj]      = sb0;
    red[grp * 64 + 32 + jj] = sb1;
    __syncthreads();
    if (t < 64) {
        float s2 = 0.0f;
        #pragma unroll
        for (int gg = 0; gg < 8; gg++) s2 += red[gg * 64 + t];
        g_sbP[sid * NN + jb + t] = s2;
    }
    // eZ fragment store: rows j = jb+mj+g (+8), cols p = nh + nt*8 + 2*t4
    #pragma unroll
    for (int nt = 0; nt < 8; nt++) {
        int p  = nh + nt * 8 + 2 * t4;
        int j0 = jb + mj + g;
        int j1 = j0 + 8;
        float2 s0 = { c[nt][0], c[nt][1] };
        float2 s1 = { c[nt][2], c[nt][3] };
        *(float2*)(g_eZP + ((size_t)sid * NN + j0) * PP + p) = s0;
        *(float2*)(g_eZP + ((size_t)sid * NN + j1) * PP + p) = s1;
    }
}

// ---------------- fused eZ-finalize + MLP + MSE loss ----------------
__device__ __forceinline__ float gelu_exact(float v) {
    return 0.5f * v * (1.0f + erff(v * 0.70710678118654752f));
}

__global__ void k_mlp(const float* __restrict__ x,
                      const float* __restrict__ We1, const float* __restrict__ be1,
                      const float* __restrict__ We2, const float* __restrict__ be2,
                      const float* __restrict__ Wd1, const float* __restrict__ bd1,
                      const float* __restrict__ Wd2, const float* __restrict__ bd2,
                      float* __restrict__ out) {
    __shared__ float We1s[32 * 129];
    __shared__ float Wd2s[128 * 33];
    __shared__ float We2s[32 * 33];
    __shared__ float Wd1s[32 * 33];
    __shared__ float be1s[32], be2s[32], bd1s[32], bd2s[128];
    int t = threadIdx.x;
    for (int idx = t; idx < 32 * 128; idx += 256)
        We1s[(idx >> 7) * 129 + (idx & 127)] = We1[idx];
    for (int idx = t; idx < 128 * 32; idx += 256)
        Wd2s[(idx >> 5) * 33 + (idx & 31)] = Wd2[idx];
    for (int idx = t; idx < 32 * 32; idx += 256) {
        We2s[(idx >> 5) * 33 + (idx & 31)] = We2[idx];
        Wd1s[(idx >> 5) * 33 + (idx & 31)] = Wd1[idx];
    }
    if (t < 32) { be1s[t] = be1[t]; be2s[t] = be2[t]; bd1s[t] = bd1[t]; }
    if (t < 128) bd2s[t] = bd2[t];
    __syncthreads();

    int lane = t & 31;
    int warp = t >> 5;
    int gw = blockIdx.x * 8 + warp;
    int nw = gridDim.x * 8;
    float part = 0.0f;

    for (int row = gw; row < NN; row += nw) {
        float den = 0.0f;
        #pragma unroll
        for (int s = 0; s < BSPLIT; s++) den += g_sbP[s * NN + row];
        float y0 = 0.0f, y1 = 0.0f, y2 = 0.0f, y3 = 0.0f;
        #pragma unroll
        for (int s = 0; s < BSPLIT; s++) {
            const float* pr = g_eZP + ((size_t)s * NN + row) * PP;
            y0 += pr[lane];       y1 += pr[32 + lane];
            y2 += pr[64 + lane];  y3 += pr[96 + lane];
        }
        if (den > 0.0f) {
            float inv = 1.0f / den;
            y0 *= inv; y1 *= inv; y2 *= inv; y3 *= inv;
        } else {
            const float* xr = x + (size_t)row * PP;
            y0 = xr[lane];      y1 = xr[32 + lane];
            y2 = xr[64 + lane]; y3 = xr[96 + lane];
        }

        float h = be1s[lane];
        const float* wrow = We1s + lane * 129;
        #pragma unroll 8
        for (int k = 0; k < 32; k++) {
            h = fmaf(__shfl_sync(0xffffffffu, y0, k), wrow[k], h);
            h = fmaf(__shfl_sync(0xffffffffu, y1, k), wrow[32 + k], h);
            h = fmaf(__shfl_sync(0xffffffffu, y2, k), wrow[64 + k], h);
            h = fmaf(__shfl_sync(0xffffffffu, y3, k), wrow[96 + k], h);
        }
        h = gelu_exact(h);

        float z = be2s[lane];
        const float* w2row = We2s + lane * 33;
        #pragma unroll
        for (int m = 0; m < 32; m++)
            z = fmaf(__shfl_sync(0xffffffffu, h, m), w2row[m], z);

        float h2 = bd1s[lane];
        const float* w3row = Wd1s + lane * 33;
        #pragma unroll
        for (int m = 0; m < 32; m++)
            h2 = fmaf(__shfl_sync(0xffffffffu, z, m), w3row[m], h2);
        h2 = gelu_exact(h2);

        float xh[4];
        #pragma unroll
        for (int q = 0; q < 4; q++) xh[q] = bd2s[q * 32 + lane];
        #pragma unroll
        for (int m = 0; m < 32; m++) {
            float hm = __shfl_sync(0xffffffffu, h2, m);
            #pragma unroll
            for (int q = 0; q < 4; q++)
                xh[q] = fmaf(hm, Wd2s[(q * 32 + lane) * 33 + m], xh[q]);
        }
        #pragma unroll
        for (int q = 0; q < 4; q++) {
            int p = q * 32 + lane;
            float s   = 1.0f / (1.0f + expf(-xh[q]));
            float dlt = x[(size_t)row * PP + p] - s;
            part = fmaf(dlt, dlt, part);
        }
    }
    #pragma unroll
    for (int o = 16; o; o >>= 1) part += __shfl_xor_sync(0xffffffffu, part, o);
    if (lane == 0) atomicAdd(out, part * (1.0f / ((float)NN * (float)PP)));
}

// ---------------- launch ----------------
extern "C" void kernel_launch(void* const* d_in, const int* in_sizes, int n_in,
                              void* d_out, int out_size) {
    const float* x   = (const float*)d_in[0];
    const float* r0  = (const float*)d_in[1];
    const float* r1  = (const float*)d_in[2];
    const float* r2  = (const float*)d_in[3];
    const float* We1 = (const float*)d_in[4];
    const float* be1 = (const float*)d_in[5];
    const float* We2 = (const float*)d_in[6];
    const float* be2 = (const float*)d_in[7];
    const float* Wd1 = (const float*)d_in[8];
    const float* bd1 = (const float*)d_in[9];
    const float* Wd2 = (const float*)d_in[10];
    const float* bd2 = (const float*)d_in[11];
    float* out = (float*)d_out;

    size_t smA = (size_t)(128 * 33 + 64 * 33 + 8 * 64) * sizeof(float);           // 27392
    size_t smB = (size_t)(64 * 132 + 32 * 132 + 64 * 33 + 32 * 66 + 8 * 64) * sizeof(float); // 69632
    cudaFuncSetAttribute(k_alpha, cudaFuncAttributeMaxDynamicSharedMemorySize, (int)smA);
    cudaFuncSetAttribute(k_beta,  cudaFuncAttributeMaxDynamicSharedMemorySize, (int)smB);

    k_zero<<<1, 1>>>(out);
    k_x2<<<NN, 32>>>(x);
    k_gram<<<dim3(32, 32), 256>>>(x);
    k_alpha<<<dim3(64, ASPLIT), 256, smA>>>(x, r0);
    k_U<<<NN, 128>>>(x);
    k_beta<<<dim3(64, BSPLIT), 256, smB>>>(x, r1, r2);
    k_mlp<<<128, 256>>>(x, We1, be1, We2, be2, Wd1, bd1, Wd2, bd2, out);
}